// round 7
// baseline (speedup 1.0000x reference)
#include <cuda_runtime.h>
#include <cmath>

// Problem constants
#define S_LEN    2048
#define D_MODEL  1024
#define NHEADS   16
#define DH       64
#define QKV_LD   3072   // 3*D
#define NTOK     4096   // B*S

// Scratch (module-static device globals: allowed, not a runtime alloc)
__device__ float g_qkv[(size_t)NTOK * QKV_LD];   // [tok, h*192 + {q:0-63,k:64-127,v:128-191}]
__device__ float g_attn[(size_t)NTOK * D_MODEL]; // [tok, h*64 + d]

// ---------------------------------------------------------------------------
// tf32 helpers
// ---------------------------------------------------------------------------
__device__ __forceinline__ unsigned f2tf32(float x) {
    unsigned u;
    asm("cvt.rna.tf32.f32 %0, %1;" : "=r"(u) : "f"(x));
    return u;
}

// D += A@B, m16n8k8, A row-major, B col-major, fp32 accum
__device__ __forceinline__ void mma_tf32(float* c, const unsigned* a, const unsigned* b) {
    asm volatile(
        "mma.sync.aligned.m16n8k8.row.col.f32.tf32.tf32.f32 "
        "{%0,%1,%2,%3}, {%4,%5,%6,%7}, {%8,%9}, {%0,%1,%2,%3};"
        : "+f"(c[0]), "+f"(c[1]), "+f"(c[2]), "+f"(c[3])
        : "r"(a[0]), "r"(a[1]), "r"(a[2]), "r"(a[3]), "r"(b[0]), "r"(b[1]));
}

// ---------------------------------------------------------------------------
// tf32 tensor-core GEMM + bias, register-prefetch pipelined.
// 128x128 CTA tile, BK=32, 256 threads = 8 warps (4x2), warp tile 32x64.
// Tile t+1 is LDG'd into registers while tile t's MMAs run, hiding L2 latency.
// ---------------------------------------------------------------------------
__global__ __launch_bounds__(256, 2)
void tf32_gemm_bias(const float* __restrict__ A, const float* __restrict__ B,
                    const float* __restrict__ bias, float* __restrict__ C,
                    int M, int N, int K) {
    __shared__ unsigned As[128][36];   // [m][k]
    __shared__ unsigned Bs[32][136];   // [k][n]

    const int tid  = threadIdx.x;
    const int warp = tid >> 5, lane = tid & 31;
    const int gid  = lane >> 2, tig = lane & 3;
    const int wrow = warp >> 1, wcol = warp & 1;
    const int bm = blockIdx.y, bn = blockIdx.x;

    // per-thread load coordinates (fixed across iterations)
    int arow[4], acol[4], brow[4], bcol[4];
#pragma unroll
    for (int c = 0; c < 4; c++) {
        int idx4 = tid + c * 256;
        arow[c] = idx4 >> 3;  acol[c] = (idx4 & 7) * 4;
        brow[c] = idx4 >> 5;  bcol[c] = (idx4 & 31) * 4;
    }

    float acc[2][8][4];
#pragma unroll
    for (int mt = 0; mt < 2; mt++)
#pragma unroll
        for (int nt = 0; nt < 8; nt++)
#pragma unroll
            for (int i = 0; i < 4; i++) acc[mt][nt][i] = 0.f;

    // Preload tile 0 into registers
    float4 pa[4], pb[4];
#pragma unroll
    for (int c = 0; c < 4; c++) {
        pa[c] = *(const float4*)(A + (size_t)(bm * 128 + arow[c]) * K + acol[c]);
        pb[c] = *(const float4*)(B + (size_t)brow[c] * N + bn * 128 + bcol[c]);
    }

    for (int k0 = 0; k0 < K; k0 += 32) {
        // STS (with tf32 cvt) of the prefetched tile
#pragma unroll
        for (int c = 0; c < 4; c++) {
            As[arow[c]][acol[c] + 0] = f2tf32(pa[c].x);
            As[arow[c]][acol[c] + 1] = f2tf32(pa[c].y);
            As[arow[c]][acol[c] + 2] = f2tf32(pa[c].z);
            As[arow[c]][acol[c] + 3] = f2tf32(pa[c].w);
            Bs[brow[c]][bcol[c] + 0] = f2tf32(pb[c].x);
            Bs[brow[c]][bcol[c] + 1] = f2tf32(pb[c].y);
            Bs[brow[c]][bcol[c] + 2] = f2tf32(pb[c].z);
            Bs[brow[c]][bcol[c] + 3] = f2tf32(pb[c].w);
        }
        __syncthreads();

        // Prefetch next tile (LDG latency overlaps the MMA phase below)
        if (k0 + 32 < K) {
#pragma unroll
            for (int c = 0; c < 4; c++) {
                pa[c] = *(const float4*)(A + (size_t)(bm * 128 + arow[c]) * K + k0 + 32 + acol[c]);
                pb[c] = *(const float4*)(B + (size_t)(k0 + 32 + brow[c]) * N + bn * 128 + bcol[c]);
            }
        }

#pragma unroll
        for (int ks = 0; ks < 4; ks++) {
            const int kk = ks * 8 + tig;
            unsigned af[2][4];
#pragma unroll
            for (int mt = 0; mt < 2; mt++) {
                int m = wrow * 32 + mt * 16 + gid;
                af[mt][0] = As[m][kk];
                af[mt][1] = As[m + 8][kk];
                af[mt][2] = As[m][kk + 4];
                af[mt][3] = As[m + 8][kk + 4];
            }
            unsigned bf[8][2];
#pragma unroll
            for (int nt = 0; nt < 8; nt++) {
                int n = wcol * 64 + nt * 8 + gid;
                bf[nt][0] = Bs[ks * 8 + tig][n];
                bf[nt][1] = Bs[ks * 8 + tig + 4][n];
            }
#pragma unroll
            for (int mt = 0; mt < 2; mt++)
#pragma unroll
                for (int nt = 0; nt < 8; nt++)
                    mma_tf32(acc[mt][nt], af[mt], bf[nt]);
        }
        __syncthreads();
    }

#pragma unroll
    for (int mt = 0; mt < 2; mt++) {
        int row0 = bm * 128 + wrow * 32 + mt * 16 + gid;
#pragma unroll
        for (int nt = 0; nt < 8; nt++) {
            int col = bn * 128 + wcol * 64 + nt * 8 + tig * 2;
            float2 bv = *(const float2*)(bias + col);
            float2 v0 = {acc[mt][nt][0] + bv.x, acc[mt][nt][1] + bv.y};
            float2 v1 = {acc[mt][nt][2] + bv.x, acc[mt][nt][3] + bv.y};
            *(float2*)(C + (size_t)row0 * N + col) = v0;
            *(float2*)(C + (size_t)(row0 + 8) * N + col) = v1;
        }
    }
}

// ---------------------------------------------------------------------------
// Flash attention with tf32 tensor cores (causal, online softmax),
// register-prefetch pipelined K/V loads.
// CTA = (qtile of 64 rows, head, batch). 4 warps; warp w owns rows w*16..+15.
// QK^T uses 2-term split of Q; P rounded to tf32 before summing l.
// ---------------------------------------------------------------------------
#define FQLD 68
#define FVLD 72
#define OFF_QH 0
#define OFF_QL (64 * FQLD)
#define OFF_KS (2 * 64 * FQLD)
#define OFF_VS (3 * 64 * FQLD)
#define OFF_PS (3 * 64 * FQLD + 64 * FVLD)
#define FLASH_SMEM_WORDS (4 * 64 * FQLD + 64 * FVLD)

__global__ __launch_bounds__(128, 2)
void flash_mma_kernel(const float* __restrict__ qkv, float* __restrict__ attn) {
    extern __shared__ unsigned fsm[];
    unsigned* Qh = fsm + OFF_QH;
    unsigned* Ql = fsm + OFF_QL;
    unsigned* Ks = fsm + OFF_KS;
    unsigned* Vs = fsm + OFF_VS;
    unsigned* Ps = fsm + OFF_PS;

    const int qt = gridDim.x - 1 - blockIdx.x;   // heavy tiles first
    const int h = blockIdx.y, b = blockIdx.z;
    const int tid = threadIdx.x;
    const int warp = tid >> 5, lane = tid & 31;
    const int gid = lane >> 2, tig = lane & 3;
    const int m0 = warp * 16;
    const int tokbase = b * S_LEN;
    const float scale = 0.125f;      // 1/sqrt(64)

    // per-thread K/V load coords (fixed across kt)
    int krow[8], kc4[8];
#pragma unroll
    for (int c = 0; c < 8; c++) {
        int i = tid + c * 128;
        krow[c] = i >> 4;  kc4[c] = (i & 15) << 2;
    }

    // Load Q tile (64x64), split into tf32 hi + lo
#pragma unroll
    for (int c = 0; c < 8; c++) {
        int row = krow[c], c4 = kc4[c];
        const float* src = qkv + (size_t)(tokbase + qt * 64 + row) * QKV_LD + h * 192;
        float4 v = *(const float4*)(src + c4);
        unsigned hx;
        hx = f2tf32(v.x); Qh[row * FQLD + c4 + 0] = hx; Ql[row * FQLD + c4 + 0] = f2tf32(v.x - __uint_as_float(hx));
        hx = f2tf32(v.y); Qh[row * FQLD + c4 + 1] = hx; Ql[row * FQLD + c4 + 1] = f2tf32(v.y - __uint_as_float(hx));
        hx = f2tf32(v.z); Qh[row * FQLD + c4 + 2] = hx; Ql[row * FQLD + c4 + 2] = f2tf32(v.z - __uint_as_float(hx));
        hx = f2tf32(v.w); Qh[row * FQLD + c4 + 3] = hx; Ql[row * FQLD + c4 + 3] = f2tf32(v.w - __uint_as_float(hx));
    }

    // Preload K/V tile 0 into registers
    float4 pk[8], pv[8];
#pragma unroll
    for (int c = 0; c < 8; c++) {
        const float* src = qkv + (size_t)(tokbase + krow[c]) * QKV_LD + h * 192;
        pk[c] = *(const float4*)(src + 64 + kc4[c]);
        pv[c] = *(const float4*)(src + 128 + kc4[c]);
    }

    float o[8][4];
    float m[2], l[2];
#pragma unroll
    for (int nt = 0; nt < 8; nt++)
#pragma unroll
        for (int i = 0; i < 4; i++) o[nt][i] = 0.f;
    m[0] = m[1] = -INFINITY;
    l[0] = l[1] = 0.f;

    for (int kt = 0; kt <= qt; kt++) {
        __syncthreads();   // prev iter's Ks/Vs reads done (1st iter: Q writes visible)

        // STS prefetched K/V (with tf32 cvt)
#pragma unroll
        for (int c = 0; c < 8; c++) {
            int row = krow[c], c4 = kc4[c];
            Ks[row * FQLD + c4 + 0] = f2tf32(pk[c].x);
            Ks[row * FQLD + c4 + 1] = f2tf32(pk[c].y);
            Ks[row * FQLD + c4 + 2] = f2tf32(pk[c].z);
            Ks[row * FQLD + c4 + 3] = f2tf32(pk[c].w);
            Vs[row * FVLD + c4 + 0] = f2tf32(pv[c].x);
            Vs[row * FVLD + c4 + 1] = f2tf32(pv[c].y);
            Vs[row * FVLD + c4 + 2] = f2tf32(pv[c].z);
            Vs[row * FVLD + c4 + 3] = f2tf32(pv[c].w);
        }
        __syncthreads();

        // Prefetch next K/V tile (overlaps entire MMA/softmax phase)
        if (kt < qt) {
#pragma unroll
            for (int c = 0; c < 8; c++) {
                const float* src = qkv +
                    (size_t)(tokbase + (kt + 1) * 64 + krow[c]) * QKV_LD + h * 192;
                pk[c] = *(const float4*)(src + 64 + kc4[c]);
                pv[c] = *(const float4*)(src + 128 + kc4[c]);
            }
        }

        // ---- S = Q K^T (split-Q: 2 MMAs per tile) ----
        float acc[8][4];
#pragma unroll
        for (int nt = 0; nt < 8; nt++)
#pragma unroll
            for (int i = 0; i < 4; i++) acc[nt][i] = 0.f;

#pragma unroll
        for (int ks = 0; ks < 8; ks++) {
            const int kk = ks * 8 + tig;
            unsigned ah[4], al[4];
            ah[0] = Qh[(m0 + gid) * FQLD + kk];
            ah[1] = Qh[(m0 + gid + 8) * FQLD + kk];
            ah[2] = Qh[(m0 + gid) * FQLD + kk + 4];
            ah[3] = Qh[(m0 + gid + 8) * FQLD + kk + 4];
            al[0] = Ql[(m0 + gid) * FQLD + kk];
            al[1] = Ql[(m0 + gid + 8) * FQLD + kk];
            al[2] = Ql[(m0 + gid) * FQLD + kk + 4];
            al[3] = Ql[(m0 + gid + 8) * FQLD + kk + 4];
#pragma unroll
            for (int nt = 0; nt < 8; nt++) {
                unsigned bb[2];
                bb[0] = Ks[(nt * 8 + gid) * FQLD + kk];
                bb[1] = Ks[(nt * 8 + gid) * FQLD + kk + 4];
                mma_tf32(acc[nt], ah, bb);
                mma_tf32(acc[nt], al, bb);
            }
        }

        // ---- scale + causal mask (diag tile only) ----
        const bool diag = (kt == qt);
#pragma unroll
        for (int nt = 0; nt < 8; nt++)
#pragma unroll
            for (int i = 0; i < 4; i++) acc[nt][i] *= scale;
        if (diag) {
            const int i0 = m0 + gid;
            const int i1 = m0 + gid + 8;
#pragma unroll
            for (int nt = 0; nt < 8; nt++) {
                int j0 = nt * 8 + 2 * tig, j1 = j0 + 1;
                if (j0 > i0) acc[nt][0] = -INFINITY;
                if (j1 > i0) acc[nt][1] = -INFINITY;
                if (j0 > i1) acc[nt][2] = -INFINITY;
                if (j1 > i1) acc[nt][3] = -INFINITY;
            }
        }

        // ---- online softmax (row spread over 4 tig-lanes) ----
#pragma unroll
        for (int r = 0; r < 2; r++) {
            float mx = -INFINITY;
#pragma unroll
            for (int nt = 0; nt < 8; nt++)
                mx = fmaxf(mx, fmaxf(acc[nt][2 * r], acc[nt][2 * r + 1]));
            mx = fmaxf(mx, __shfl_xor_sync(0xffffffffu, mx, 1));
            mx = fmaxf(mx, __shfl_xor_sync(0xffffffffu, mx, 2));
            float mn = fmaxf(m[r], mx);

            float ls = 0.f;
            const int prow = (m0 + gid + 8 * r) * FQLD;
#pragma unroll
            for (int nt = 0; nt < 8; nt++) {
                float p0 = __expf(acc[nt][2 * r] - mn);
                float p1 = __expf(acc[nt][2 * r + 1] - mn);
                unsigned t0 = f2tf32(p0), t1 = f2tf32(p1);
                ls += __uint_as_float(t0) + __uint_as_float(t1);
                *(uint2*)(Ps + prow + nt * 8 + 2 * tig) = make_uint2(t0, t1);
            }
            ls += __shfl_xor_sync(0xffffffffu, ls, 1);
            ls += __shfl_xor_sync(0xffffffffu, ls, 2);

            float f = __expf(m[r] - mn);
            l[r] = l[r] * f + ls;
            m[r] = mn;
#pragma unroll
            for (int nt = 0; nt < 8; nt++) {
                o[nt][2 * r] *= f;
                o[nt][2 * r + 1] *= f;
            }
        }
        __syncwarp();   // warp-private Ps visible

        // ---- O += P @ V ----
#pragma unroll
        for (int ks = 0; ks < 8; ks++) {
            const int kk = ks * 8 + tig;
            unsigned a[4];
            a[0] = Ps[(m0 + gid) * FQLD + kk];
            a[1] = Ps[(m0 + gid + 8) * FQLD + kk];
            a[2] = Ps[(m0 + gid) * FQLD + kk + 4];
            a[3] = Ps[(m0 + gid + 8) * FQLD + kk + 4];
#pragma unroll
            for (int nt = 0; nt < 8; nt++) {
                unsigned bb[2];
                bb[0] = Vs[kk * FVLD + nt * 8 + gid];
                bb[1] = Vs[(kk + 4) * FVLD + nt * 8 + gid];
                mma_tf32(o[nt], a, bb);
            }
        }
        __syncwarp();   // Ps reads done before next iter's overwrite
    }

    // ---- normalize + write [tok, h*64+d] ----
    const float inv0 = 1.0f / l[0], inv1 = 1.0f / l[1];
    const int row0 = tokbase + qt * 64 + m0 + gid;
#pragma unroll
    for (int nt = 0; nt < 8; nt++) {
        int col = h * DH + nt * 8 + 2 * tig;
        float2 v0 = {o[nt][0] * inv0, o[nt][1] * inv0};
        float2 v1 = {o[nt][2] * inv1, o[nt][3] * inv1};
        *(float2*)(attn + (size_t)row0 * D_MODEL + col) = v0;
        *(float2*)(attn + (size_t)(row0 + 8) * D_MODEL + col) = v1;
    }
}

// ---------------------------------------------------------------------------
// Launch
// ---------------------------------------------------------------------------
extern "C" void kernel_launch(void* const* d_in, const int* in_sizes, int n_in,
                              void* d_out, int out_size) {
    const float* x    = (const float*)d_in[0];   // [2,2048,1024]
    const float* Wqkv = (const float*)d_in[1];   // [1024,3072]
    const float* bqkv = (const float*)d_in[2];   // [3072]
    const float* Wout = (const float*)d_in[3];   // [1024,1024]
    const float* bout = (const float*)d_in[4];   // [1024]
    float* out = (float*)d_out;                  // [2,2048,1024]

    float* qkv;  cudaGetSymbolAddress((void**)&qkv,  g_qkv);
    float* attn; cudaGetSymbolAddress((void**)&attn, g_attn);

    const int flash_smem = FLASH_SMEM_WORDS * (int)sizeof(unsigned);  // 88064 B
    cudaFuncSetAttribute(flash_mma_kernel, cudaFuncAttributeMaxDynamicSharedMemorySize,
                         flash_smem);

    // 1) QKV projection (tf32 tensor cores, pipelined)
    {
        dim3 grid(QKV_LD / 128, NTOK / 128);
        tf32_gemm_bias<<<grid, 256>>>(x, Wqkv, bqkv, qkv, NTOK, QKV_LD, D_MODEL);
    }

    // 2) Causal flash attention (tf32 tensor cores, pipelined)
    {
        dim3 grid(S_LEN / 64, NHEADS, 2);
        flash_mma_kernel<<<grid, 128, flash_smem>>>(qkv, attn);
    }

    // 3) Output projection (tf32 tensor cores, pipelined)
    {
        dim3 grid(D_MODEL / 128, NTOK / 128);
        tf32_gemm_bias<<<grid, 256>>>(attn, Wout, bout, out, NTOK, D_MODEL, D_MODEL);
    }
}

// round 9
// speedup vs baseline: 1.0308x; 1.0308x over previous
#include <cuda_runtime.h>
#include <cmath>

// Problem constants
#define S_LEN    2048
#define D_MODEL  1024
#define NHEADS   16
#define DH       64
#define QKV_LD   3072   // 3*D
#define NTOK     4096   // B*S

// Scratch (module-static device globals: allowed, not a runtime alloc)
__device__ float    g_qkv[(size_t)NTOK * QKV_LD];     // fp32 qkv projection
__device__ unsigned g_attn[(size_t)NTOK * D_MODEL];   // tf32-bit attention output
__device__ unsigned g_xt[(size_t)NTOK * D_MODEL];     // tf32-bit x
__device__ unsigned g_wqkvt[(size_t)D_MODEL * QKV_LD];// tf32-bit Wqkv
__device__ unsigned g_woutt[(size_t)D_MODEL * D_MODEL];// tf32-bit Wout

// ---------------------------------------------------------------------------
// tf32 helpers
// ---------------------------------------------------------------------------
__device__ __forceinline__ unsigned f2tf32(float x) {
    unsigned u;
    asm("cvt.rna.tf32.f32 %0, %1;" : "=r"(u) : "f"(x));
    return u;
}

// D += A@B, m16n8k8, A row-major, B col-major, fp32 accum
__device__ __forceinline__ void mma_tf32(float* c, const unsigned* a, const unsigned* b) {
    asm volatile(
        "mma.sync.aligned.m16n8k8.row.col.f32.tf32.tf32.f32 "
        "{%0,%1,%2,%3}, {%4,%5,%6,%7}, {%8,%9}, {%0,%1,%2,%3};"
        : "+f"(c[0]), "+f"(c[1]), "+f"(c[2]), "+f"(c[3])
        : "r"(a[0]), "r"(a[1]), "r"(a[2]), "r"(a[3]), "r"(b[0]), "r"(b[1]));
}

__device__ __forceinline__ void cp_async16(unsigned smem_addr, const void* gptr) {
    asm volatile("cp.async.cg.shared.global [%0], [%1], 16;"
                 :: "r"(smem_addr), "l"(gptr));
}
__device__ __forceinline__ void cp_commit() {
    asm volatile("cp.async.commit_group;");
}
__device__ __forceinline__ void cp_wait0() {
    asm volatile("cp.async.wait_group 0;");
}

// ---------------------------------------------------------------------------
// Elementwise tf32 pre-convert (fp32 -> tf32-rounded bits)
// ---------------------------------------------------------------------------
__global__ void cvt_tf32_kernel(const float4* __restrict__ src,
                                uint4* __restrict__ dst, int n4) {
    int i = blockIdx.x * blockDim.x + threadIdx.x;
    if (i < n4) {
        float4 v = src[i];
        dst[i] = make_uint4(f2tf32(v.x), f2tf32(v.y), f2tf32(v.z), f2tf32(v.w));
    }
}

// ---------------------------------------------------------------------------
// tf32 tensor-core GEMM + bias; inputs pre-converted to tf32 bits.
// cp.async double-buffered smem pipeline; mainloop is LDS + MMA only.
// 128x128 CTA tile, BK=32, 256 threads = 8 warps (4x2), warp tile 32x64.
// As: [128][36] (bank 4m+k), Bs: [32][136] (bank 8k+n) per buffer.
// ---------------------------------------------------------------------------
#define AS_W 36
#define BS_W 136
#define BUF_WORDS (128 * AS_W + 32 * BS_W)   // 8960 words per stage
#define GEMM_SMEM_BYTES (2 * BUF_WORDS * 4)  // 71680

__global__ __launch_bounds__(256, 2)
void tf32_gemm_bias(const unsigned* __restrict__ A, const unsigned* __restrict__ B,
                    const float* __restrict__ bias, float* __restrict__ C,
                    int M, int N, int K) {
    extern __shared__ unsigned gsm[];

    const int tid  = threadIdx.x;
    const int warp = tid >> 5, lane = tid & 31;
    const int gid  = lane >> 2, tig = lane & 3;
    const int wrow = warp >> 1, wcol = warp & 1;
    const int bm = blockIdx.y, bn = blockIdx.x;

    // per-thread async-copy coordinates (fixed across iterations)
    int arow[4], acol[4], brow[4], bcol[4];
#pragma unroll
    for (int c = 0; c < 4; c++) {
        int idx4 = tid + c * 256;
        arow[c] = idx4 >> 3;  acol[c] = (idx4 & 7) * 4;
        brow[c] = idx4 >> 5;  bcol[c] = (idx4 & 31) * 4;
    }

    const unsigned smem_base = (unsigned)__cvta_generic_to_shared(gsm);

    // issue one tile's 8 cp.asyncs into buffer s
    auto issue_tile = [&](int s, int k0) {
        unsigned as_b = smem_base + (unsigned)(s * BUF_WORDS) * 4u;
        unsigned bs_b = as_b + 128u * AS_W * 4u;
#pragma unroll
        for (int c = 0; c < 4; c++) {
            cp_async16(as_b + (unsigned)(arow[c] * AS_W + acol[c]) * 4u,
                       A + (size_t)(bm * 128 + arow[c]) * K + k0 + acol[c]);
            cp_async16(bs_b + (unsigned)(brow[c] * BS_W + bcol[c]) * 4u,
                       B + (size_t)(k0 + brow[c]) * N + bn * 128 + bcol[c]);
        }
        cp_commit();
    };

    float acc[2][8][4];
#pragma unroll
    for (int mt = 0; mt < 2; mt++)
#pragma unroll
        for (int nt = 0; nt < 8; nt++)
#pragma unroll
            for (int i = 0; i < 4; i++) acc[mt][nt][i] = 0.f;

    issue_tile(0, 0);

    int s = 0;
    for (int k0 = 0; k0 < K; k0 += 32) {
        cp_wait0();
        __syncthreads();     // buffer s ready; also guards WAR on buffer s^1
        if (k0 + 32 < K) issue_tile(s ^ 1, k0 + 32);

        const unsigned* As = gsm + s * BUF_WORDS;          // [128][36]
        const unsigned* Bs = As + 128 * AS_W;              // [32][136]

#pragma unroll
        for (int ks = 0; ks < 4; ks++) {
            const int kk = ks * 8 + tig;
            unsigned af[2][4];
#pragma unroll
            for (int mt = 0; mt < 2; mt++) {
                int m = wrow * 32 + mt * 16 + gid;
                af[mt][0] = As[m * AS_W + kk];
                af[mt][1] = As[(m + 8) * AS_W + kk];
                af[mt][2] = As[m * AS_W + kk + 4];
                af[mt][3] = As[(m + 8) * AS_W + kk + 4];
            }
            unsigned bf[8][2];
#pragma unroll
            for (int nt = 0; nt < 8; nt++) {
                int n = wcol * 64 + nt * 8 + gid;
                bf[nt][0] = Bs[kk * BS_W + n];
                bf[nt][1] = Bs[(kk + 4) * BS_W + n];
            }
#pragma unroll
            for (int mt = 0; mt < 2; mt++)
#pragma unroll
                for (int nt = 0; nt < 8; nt++)
                    mma_tf32(acc[mt][nt], af[mt], bf[nt]);
        }
        s ^= 1;
    }

#pragma unroll
    for (int mt = 0; mt < 2; mt++) {
        int row0 = bm * 128 + wrow * 32 + mt * 16 + gid;
#pragma unroll
        for (int nt = 0; nt < 8; nt++) {
            int col = bn * 128 + wcol * 64 + nt * 8 + tig * 2;
            float2 bv = *(const float2*)(bias + col);
            float2 v0 = {acc[mt][nt][0] + bv.x, acc[mt][nt][1] + bv.y};
            float2 v1 = {acc[mt][nt][2] + bv.x, acc[mt][nt][3] + bv.y};
            *(float2*)(C + (size_t)row0 * N + col) = v0;
            *(float2*)(C + (size_t)(row0 + 8) * N + col) = v1;
        }
    }
}

// ---------------------------------------------------------------------------
// Flash attention with tf32 tensor cores (R5-validated structure).
// Epilogue writes tf32-rounded bits (feeds pre-converted GEMM3 directly).
// ---------------------------------------------------------------------------
#define FQLD 68
#define FVLD 72
#define OFF_QH 0
#define OFF_QL (64 * FQLD)
#define OFF_KS (2 * 64 * FQLD)
#define OFF_VS (3 * 64 * FQLD)
#define OFF_PS (3 * 64 * FQLD + 64 * FVLD)
#define FLASH_SMEM_WORDS (4 * 64 * FQLD + 64 * FVLD)

__global__ __launch_bounds__(128, 2)
void flash_mma_kernel(const float* __restrict__ qkv, unsigned* __restrict__ attn) {
    extern __shared__ unsigned fsm[];
    unsigned* Qh = fsm + OFF_QH;
    unsigned* Ql = fsm + OFF_QL;
    unsigned* Ks = fsm + OFF_KS;
    unsigned* Vs = fsm + OFF_VS;
    unsigned* Ps = fsm + OFF_PS;

    const int qt = gridDim.x - 1 - blockIdx.x;   // heavy tiles first
    const int h = blockIdx.y, b = blockIdx.z;
    const int tid = threadIdx.x;
    const int warp = tid >> 5, lane = tid & 31;
    const int gid = lane >> 2, tig = lane & 3;
    const int m0 = warp * 16;
    const int tokbase = b * S_LEN;
    const float scale = 0.125f;      // 1/sqrt(64)

    // Load Q tile (64x64), split into tf32 hi + lo
#pragma unroll
    for (int c = 0; c < 8; c++) {
        int i = tid + c * 128;
        int row = i >> 4, c4 = (i & 15) << 2;
        const float* src = qkv + (size_t)(tokbase + qt * 64 + row) * QKV_LD + h * 192;
        float4 v = *(const float4*)(src + c4);
        unsigned hx;
        hx = f2tf32(v.x); Qh[row * FQLD + c4 + 0] = hx; Ql[row * FQLD + c4 + 0] = f2tf32(v.x - __uint_as_float(hx));
        hx = f2tf32(v.y); Qh[row * FQLD + c4 + 1] = hx; Ql[row * FQLD + c4 + 1] = f2tf32(v.y - __uint_as_float(hx));
        hx = f2tf32(v.z); Qh[row * FQLD + c4 + 2] = hx; Ql[row * FQLD + c4 + 2] = f2tf32(v.z - __uint_as_float(hx));
        hx = f2tf32(v.w); Qh[row * FQLD + c4 + 3] = hx; Ql[row * FQLD + c4 + 3] = f2tf32(v.w - __uint_as_float(hx));
    }

    float o[8][4];
    float m[2], l[2];
#pragma unroll
    for (int nt = 0; nt < 8; nt++)
#pragma unroll
        for (int i = 0; i < 4; i++) o[nt][i] = 0.f;
    m[0] = m[1] = -INFINITY;
    l[0] = l[1] = 0.f;

    for (int kt = 0; kt <= qt; kt++) {
        __syncthreads();

        // Load K,V tiles (64x64 each), tf32-convert
#pragma unroll
        for (int c = 0; c < 8; c++) {
            int i = tid + c * 128;
            int row = i >> 4, c4 = (i & 15) << 2;
            const float* src = qkv + (size_t)(tokbase + kt * 64 + row) * QKV_LD + h * 192;
            float4 kv = *(const float4*)(src + 64 + c4);
            float4 vv = *(const float4*)(src + 128 + c4);
            Ks[row * FQLD + c4 + 0] = f2tf32(kv.x);
            Ks[row * FQLD + c4 + 1] = f2tf32(kv.y);
            Ks[row * FQLD + c4 + 2] = f2tf32(kv.z);
            Ks[row * FQLD + c4 + 3] = f2tf32(kv.w);
            Vs[row * FVLD + c4 + 0] = f2tf32(vv.x);
            Vs[row * FVLD + c4 + 1] = f2tf32(vv.y);
            Vs[row * FVLD + c4 + 2] = f2tf32(vv.z);
            Vs[row * FVLD + c4 + 3] = f2tf32(vv.w);
        }
        __syncthreads();

        // ---- S = Q K^T (split-Q: 2 MMAs per tile) ----
        float acc[8][4];
#pragma unroll
        for (int nt = 0; nt < 8; nt++)
#pragma unroll
            for (int i = 0; i < 4; i++) acc[nt][i] = 0.f;

#pragma unroll
        for (int ks = 0; ks < 8; ks++) {
            const int kk = ks * 8 + tig;
            unsigned ah[4], al[4];
            ah[0] = Qh[(m0 + gid) * FQLD + kk];
            ah[1] = Qh[(m0 + gid + 8) * FQLD + kk];
            ah[2] = Qh[(m0 + gid) * FQLD + kk + 4];
            ah[3] = Qh[(m0 + gid + 8) * FQLD + kk + 4];
            al[0] = Ql[(m0 + gid) * FQLD + kk];
            al[1] = Ql[(m0 + gid + 8) * FQLD + kk];
            al[2] = Ql[(m0 + gid) * FQLD + kk + 4];
            al[3] = Ql[(m0 + gid + 8) * FQLD + kk + 4];
#pragma unroll
            for (int nt = 0; nt < 8; nt++) {
                unsigned bb[2];
                bb[0] = Ks[(nt * 8 + gid) * FQLD + kk];
                bb[1] = Ks[(nt * 8 + gid) * FQLD + kk + 4];
                mma_tf32(acc[nt], ah, bb);
                mma_tf32(acc[nt], al, bb);
            }
        }

        // ---- scale + causal mask (diag tile only) ----
        const bool diag = (kt == qt);
#pragma unroll
        for (int nt = 0; nt < 8; nt++)
#pragma unroll
            for (int i = 0; i < 4; i++) acc[nt][i] *= scale;
        if (diag) {
            const int i0 = m0 + gid;
            const int i1 = m0 + gid + 8;
#pragma unroll
            for (int nt = 0; nt < 8; nt++) {
                int j0 = nt * 8 + 2 * tig, j1 = j0 + 1;
                if (j0 > i0) acc[nt][0] = -INFINITY;
                if (j1 > i0) acc[nt][1] = -INFINITY;
                if (j0 > i1) acc[nt][2] = -INFINITY;
                if (j1 > i1) acc[nt][3] = -INFINITY;
            }
        }

        // ---- online softmax (row spread over 4 tig-lanes) ----
#pragma unroll
        for (int r = 0; r < 2; r++) {
            float mx = -INFINITY;
#pragma unroll
            for (int nt = 0; nt < 8; nt++)
                mx = fmaxf(mx, fmaxf(acc[nt][2 * r], acc[nt][2 * r + 1]));
            mx = fmaxf(mx, __shfl_xor_sync(0xffffffffu, mx, 1));
            mx = fmaxf(mx, __shfl_xor_sync(0xffffffffu, mx, 2));
            float mn = fmaxf(m[r], mx);

            float ls = 0.f;
            const int prow = (m0 + gid + 8 * r) * FQLD;
#pragma unroll
            for (int nt = 0; nt < 8; nt++) {
                float p0 = __expf(acc[nt][2 * r] - mn);
                float p1 = __expf(acc[nt][2 * r + 1] - mn);
                unsigned t0 = f2tf32(p0), t1 = f2tf32(p1);
                ls += __uint_as_float(t0) + __uint_as_float(t1);
                *(uint2*)(Ps + prow + nt * 8 + 2 * tig) = make_uint2(t0, t1);
            }
            ls += __shfl_xor_sync(0xffffffffu, ls, 1);
            ls += __shfl_xor_sync(0xffffffffu, ls, 2);

            float f = __expf(m[r] - mn);
            l[r] = l[r] * f + ls;
            m[r] = mn;
#pragma unroll
            for (int nt = 0; nt < 8; nt++) {
                o[nt][2 * r] *= f;
                o[nt][2 * r + 1] *= f;
            }
        }
        __syncwarp();

        // ---- O += P @ V ----
#pragma unroll
        for (int ks = 0; ks < 8; ks++) {
            const int kk = ks * 8 + tig;
            unsigned a[4];
            a[0] = Ps[(m0 + gid) * FQLD + kk];
            a[1] = Ps[(m0 + gid + 8) * FQLD + kk];
            a[2] = Ps[(m0 + gid) * FQLD + kk + 4];
            a[3] = Ps[(m0 + gid + 8) * FQLD + kk + 4];
#pragma unroll
            for (int nt = 0; nt < 8; nt++) {
                unsigned bb[2];
                bb[0] = Vs[kk * FVLD + nt * 8 + gid];
                bb[1] = Vs[(kk + 4) * FVLD + nt * 8 + gid];
                mma_tf32(o[nt], a, bb);
            }
        }
        __syncwarp();
    }

    // ---- normalize + write tf32-rounded bits to [tok, h*64+d] ----
    const float inv0 = 1.0f / l[0], inv1 = 1.0f / l[1];
    const int row0 = tokbase + qt * 64 + m0 + gid;
#pragma unroll
    for (int nt = 0; nt < 8; nt++) {
        int col = h * DH + nt * 8 + 2 * tig;
        uint2 v0 = make_uint2(f2tf32(o[nt][0] * inv0), f2tf32(o[nt][1] * inv0));
        uint2 v1 = make_uint2(f2tf32(o[nt][2] * inv1), f2tf32(o[nt][3] * inv1));
        *(uint2*)(attn + (size_t)row0 * D_MODEL + col) = v0;
        *(uint2*)(attn + (size_t)(row0 + 8) * D_MODEL + col) = v1;
    }
}

// ---------------------------------------------------------------------------
// Launch
// ---------------------------------------------------------------------------
extern "C" void kernel_launch(void* const* d_in, const int* in_sizes, int n_in,
                              void* d_out, int out_size) {
    const float* x    = (const float*)d_in[0];   // [2,2048,1024]
    const float* Wqkv = (const float*)d_in[1];   // [1024,3072]
    const float* bqkv = (const float*)d_in[2];   // [3072]
    const float* Wout = (const float*)d_in[3];   // [1024,1024]
    const float* bout = (const float*)d_in[4];   // [1024]
    float* out = (float*)d_out;                  // [2,2048,1024]

    float*    qkv;   cudaGetSymbolAddress((void**)&qkv,   g_qkv);
    unsigned* attn;  cudaGetSymbolAddress((void**)&attn,  g_attn);
    unsigned* xt;    cudaGetSymbolAddress((void**)&xt,    g_xt);
    unsigned* wqkvt; cudaGetSymbolAddress((void**)&wqkvt, g_wqkvt);
    unsigned* woutt; cudaGetSymbolAddress((void**)&woutt, g_woutt);

    cudaFuncSetAttribute(tf32_gemm_bias, cudaFuncAttributeMaxDynamicSharedMemorySize,
                         GEMM_SMEM_BYTES);
    const int flash_smem = FLASH_SMEM_WORDS * (int)sizeof(unsigned);  // 88064 B
    cudaFuncSetAttribute(flash_mma_kernel, cudaFuncAttributeMaxDynamicSharedMemorySize,
                         flash_smem);

    // 0) Pre-convert x, Wqkv, Wout to tf32 bits
    {
        int n4;
        n4 = NTOK * D_MODEL / 4;
        cvt_tf32_kernel<<<(n4 + 255) / 256, 256>>>((const float4*)x, (uint4*)xt, n4);
        n4 = D_MODEL * QKV_LD / 4;
        cvt_tf32_kernel<<<(n4 + 255) / 256, 256>>>((const float4*)Wqkv, (uint4*)wqkvt, n4);
        n4 = D_MODEL * D_MODEL / 4;
        cvt_tf32_kernel<<<(n4 + 255) / 256, 256>>>((const float4*)Wout, (uint4*)woutt, n4);
    }

    // 1) QKV projection (tf32 tensor cores, cp.async pipelined)
    {
        dim3 grid(QKV_LD / 128, NTOK / 128);
        tf32_gemm_bias<<<grid, 256, GEMM_SMEM_BYTES>>>(xt, wqkvt, bqkv, qkv,
                                                       NTOK, QKV_LD, D_MODEL);
    }

    // 2) Causal flash attention (tf32 tensor cores); writes tf32 bits
    {
        dim3 grid(S_LEN / 64, NHEADS, 2);
        flash_mma_kernel<<<grid, 128, flash_smem>>>(qkv, attn);
    }

    // 3) Output projection (tf32 tensor cores, cp.async pipelined)
    {
        dim3 grid(D_MODEL / 128, NTOK / 128);
        tf32_gemm_bias<<<grid, 256, GEMM_SMEM_BYTES>>>(attn, woutt, bout, out,
                                                       NTOK, D_MODEL, D_MODEL);
    }
}

// round 10
// speedup vs baseline: 1.2423x; 1.2051x over previous
#include <cuda_runtime.h>
#include <cmath>

// Problem constants
#define S_LEN    2048
#define D_MODEL  1024
#define NHEADS   16
#define DH       64
#define QKV_LD   3072   // 3*D
#define NTOK     4096   // B*S

// Scratch (module-static device globals)
__device__ unsigned g_qkv[(size_t)NTOK * QKV_LD];     // tf32-bit qkv projection
__device__ unsigned g_attn[(size_t)NTOK * D_MODEL];   // tf32-bit attention output
__device__ unsigned g_xt[(size_t)NTOK * D_MODEL];     // tf32-bit x
__device__ unsigned g_wqkvt[(size_t)D_MODEL * QKV_LD];// tf32-bit Wqkv
__device__ unsigned g_woutt[(size_t)D_MODEL * D_MODEL];// tf32-bit Wout

// ---------------------------------------------------------------------------
// tf32 helpers
// ---------------------------------------------------------------------------
__device__ __forceinline__ unsigned f2tf32(float x) {
    unsigned u;
    asm("cvt.rna.tf32.f32 %0, %1;" : "=r"(u) : "f"(x));
    return u;
}

// D += A@B, m16n8k8, A row-major, B col-major, fp32 accum
__device__ __forceinline__ void mma_tf32(float* c, const unsigned* a, const unsigned* b) {
    asm volatile(
        "mma.sync.aligned.m16n8k8.row.col.f32.tf32.tf32.f32 "
        "{%0,%1,%2,%3}, {%4,%5,%6,%7}, {%8,%9}, {%0,%1,%2,%3};"
        : "+f"(c[0]), "+f"(c[1]), "+f"(c[2]), "+f"(c[3])
        : "r"(a[0]), "r"(a[1]), "r"(a[2]), "r"(a[3]), "r"(b[0]), "r"(b[1]));
}

__device__ __forceinline__ void cp_async16(unsigned smem_addr, const void* gptr) {
    asm volatile("cp.async.cg.shared.global [%0], [%1], 16;"
                 :: "r"(smem_addr), "l"(gptr));
}
__device__ __forceinline__ void cp_commit() {
    asm volatile("cp.async.commit_group;");
}
__device__ __forceinline__ void cp_wait0() {
    asm volatile("cp.async.wait_group 0;");
}

// ---------------------------------------------------------------------------
// Fused elementwise tf32 pre-convert for x, Wqkv, Wout (one launch)
// ---------------------------------------------------------------------------
__global__ void cvt_tf32_fused(const float4* s0, uint4* d0, int n0,
                               const float4* s1, uint4* d1, int n1,
                               const float4* s2, uint4* d2, int n2) {
    int i = blockIdx.x * blockDim.x + threadIdx.x;
    const float4* s; uint4* d; int j;
    if (i < n0)            { s = s0; d = d0; j = i; }
    else if (i < n0 + n1)  { s = s1; d = d1; j = i - n0; }
    else if (i < n0+n1+n2) { s = s2; d = d2; j = i - n0 - n1; }
    else return;
    float4 v = s[j];
    d[j] = make_uint4(f2tf32(v.x), f2tf32(v.y), f2tf32(v.z), f2tf32(v.w));
}

// ---------------------------------------------------------------------------
// tf32 tensor-core GEMM + bias; inputs pre-converted tf32 bits.
// cp.async double-buffered; mainloop = LDS + MMA only. (validated R7)
// TF32OUT: epilogue writes tf32-rounded bits (for qkv feeding flash).
// ---------------------------------------------------------------------------
#define AS_W 36
#define BS_W 136
#define BUF_WORDS (128 * AS_W + 32 * BS_W)   // 8960 words per stage
#define GEMM_SMEM_BYTES (2 * BUF_WORDS * 4)  // 71680

template<int TF32OUT>
__global__ __launch_bounds__(256, 2)
void tf32_gemm_bias(const unsigned* __restrict__ A, const unsigned* __restrict__ B,
                    const float* __restrict__ bias, void* __restrict__ Cv,
                    int M, int N, int K) {
    extern __shared__ unsigned gsm[];

    const int tid  = threadIdx.x;
    const int warp = tid >> 5, lane = tid & 31;
    const int gid  = lane >> 2, tig = lane & 3;
    const int wrow = warp >> 1, wcol = warp & 1;
    const int bm = blockIdx.y, bn = blockIdx.x;

    int arow[4], acol[4], brow[4], bcol[4];
#pragma unroll
    for (int c = 0; c < 4; c++) {
        int idx4 = tid + c * 256;
        arow[c] = idx4 >> 3;  acol[c] = (idx4 & 7) * 4;
        brow[c] = idx4 >> 5;  bcol[c] = (idx4 & 31) * 4;
    }

    const unsigned smem_base = (unsigned)__cvta_generic_to_shared(gsm);

    auto issue_tile = [&](int s, int k0) {
        unsigned as_b = smem_base + (unsigned)(s * BUF_WORDS) * 4u;
        unsigned bs_b = as_b + 128u * AS_W * 4u;
#pragma unroll
        for (int c = 0; c < 4; c++) {
            cp_async16(as_b + (unsigned)(arow[c] * AS_W + acol[c]) * 4u,
                       A + (size_t)(bm * 128 + arow[c]) * K + k0 + acol[c]);
            cp_async16(bs_b + (unsigned)(brow[c] * BS_W + bcol[c]) * 4u,
                       B + (size_t)(k0 + brow[c]) * N + bn * 128 + bcol[c]);
        }
        cp_commit();
    };

    float acc[2][8][4];
#pragma unroll
    for (int mt = 0; mt < 2; mt++)
#pragma unroll
        for (int nt = 0; nt < 8; nt++)
#pragma unroll
            for (int i = 0; i < 4; i++) acc[mt][nt][i] = 0.f;

    issue_tile(0, 0);

    int s = 0;
    for (int k0 = 0; k0 < K; k0 += 32) {
        cp_wait0();
        __syncthreads();
        if (k0 + 32 < K) issue_tile(s ^ 1, k0 + 32);

        const unsigned* As = gsm + s * BUF_WORDS;
        const unsigned* Bs = As + 128 * AS_W;

#pragma unroll
        for (int ks = 0; ks < 4; ks++) {
            const int kk = ks * 8 + tig;
            unsigned af[2][4];
#pragma unroll
            for (int mt = 0; mt < 2; mt++) {
                int m = wrow * 32 + mt * 16 + gid;
                af[mt][0] = As[m * AS_W + kk];
                af[mt][1] = As[(m + 8) * AS_W + kk];
                af[mt][2] = As[m * AS_W + kk + 4];
                af[mt][3] = As[(m + 8) * AS_W + kk + 4];
            }
            unsigned bf[8][2];
#pragma unroll
            for (int nt = 0; nt < 8; nt++) {
                int n = wcol * 64 + nt * 8 + gid;
                bf[nt][0] = Bs[kk * BS_W + n];
                bf[nt][1] = Bs[(kk + 4) * BS_W + n];
            }
#pragma unroll
            for (int mt = 0; mt < 2; mt++)
#pragma unroll
                for (int nt = 0; nt < 8; nt++)
                    mma_tf32(acc[mt][nt], af[mt], bf[nt]);
        }
        s ^= 1;
    }

#pragma unroll
    for (int mt = 0; mt < 2; mt++) {
        int row0 = bm * 128 + wrow * 32 + mt * 16 + gid;
#pragma unroll
        for (int nt = 0; nt < 8; nt++) {
            int col = bn * 128 + wcol * 64 + nt * 8 + tig * 2;
            float2 bv = *(const float2*)(bias + col);
            float c0 = acc[mt][nt][0] + bv.x, c1 = acc[mt][nt][1] + bv.y;
            float c2 = acc[mt][nt][2] + bv.x, c3 = acc[mt][nt][3] + bv.y;
            if (TF32OUT) {
                unsigned* C = (unsigned*)Cv;
                *(uint2*)(C + (size_t)row0 * N + col) = make_uint2(f2tf32(c0), f2tf32(c1));
                *(uint2*)(C + (size_t)(row0 + 8) * N + col) = make_uint2(f2tf32(c2), f2tf32(c3));
            } else {
                float* C = (float*)Cv;
                *(float2*)(C + (size_t)row0 * N + col) = make_float2(c0, c1);
                *(float2*)(C + (size_t)(row0 + 8) * N + col) = make_float2(c2, c3);
            }
        }
    }
}

// ---------------------------------------------------------------------------
// Flash attention, tf32 tensor cores (causal, online softmax).
//  - qkv pre-converted to tf32 bits by GEMM1 epilogue (no cvt in loop)
//  - Q fragments held in registers (loop-invariant)
//  - K/V tiles cp.async double-buffered
//  - no split-Q; P tf32-rounded before summing l (self-consistent PV)
// CTA = (qtile 64 rows, head, batch), 4 warps x 16 rows.
// ---------------------------------------------------------------------------
#define FKLD 68
#define FVLD 72
#define KV_STAGE_WORDS (64 * FKLD + 64 * FVLD)          // 8960
#define OFF_PS (2 * KV_STAGE_WORDS)                     // Ps after 2 stages
#define FLASH_SMEM_WORDS (2 * KV_STAGE_WORDS + 64 * FKLD) // 22272 (89088 B)

__global__ __launch_bounds__(128, 2)
void flash_mma_kernel(const unsigned* __restrict__ qkv, unsigned* __restrict__ attn) {
    extern __shared__ unsigned fsm[];
    unsigned* Ps = fsm + OFF_PS;

    const int qt = gridDim.x - 1 - blockIdx.x;   // heavy tiles first
    const int h = blockIdx.y, b = blockIdx.z;
    const int tid = threadIdx.x;
    const int warp = tid >> 5, lane = tid & 31;
    const int gid = lane >> 2, tig = lane & 3;
    const int m0 = warp * 16;
    const int tokbase = b * S_LEN;
    const float scale = 0.125f;      // 1/sqrt(64)

    // per-thread K/V async-copy coords
    int krow[8], kc4[8];
#pragma unroll
    for (int c = 0; c < 8; c++) {
        int i = tid + c * 128;
        krow[c] = i >> 4;  kc4[c] = (i & 15) << 2;
    }

    const unsigned smem_base = (unsigned)__cvta_generic_to_shared(fsm);

    auto issue_kv = [&](int s, int kt) {
        unsigned ks_b = smem_base + (unsigned)(s * KV_STAGE_WORDS) * 4u;
        unsigned vs_b = ks_b + 64u * FKLD * 4u;
#pragma unroll
        for (int c = 0; c < 8; c++) {
            const unsigned* src =
                qkv + (size_t)(tokbase + kt * 64 + krow[c]) * QKV_LD + h * 192;
            cp_async16(ks_b + (unsigned)(krow[c] * FKLD + kc4[c]) * 4u, src + 64 + kc4[c]);
            cp_async16(vs_b + (unsigned)(krow[c] * FVLD + kc4[c]) * 4u, src + 128 + kc4[c]);
        }
        cp_commit();
    };

    // ---- Q fragments in registers (loop-invariant) ----
    unsigned qf[8][4];
    {
        const size_t r0 = (size_t)(tokbase + qt * 64 + m0 + gid) * QKV_LD + h * 192;
        const size_t r1 = r0 + 8 * QKV_LD;
#pragma unroll
        for (int ks = 0; ks < 8; ks++) {
            int col = ks * 8 + tig;
            qf[ks][0] = qkv[r0 + col];
            qf[ks][1] = qkv[r1 + col];
            qf[ks][2] = qkv[r0 + col + 4];
            qf[ks][3] = qkv[r1 + col + 4];
        }
    }

    issue_kv(0, 0);

    float o[8][4];
    float m[2], l[2];
#pragma unroll
    for (int nt = 0; nt < 8; nt++)
#pragma unroll
        for (int i = 0; i < 4; i++) o[nt][i] = 0.f;
    m[0] = m[1] = -INFINITY;
    l[0] = l[1] = 0.f;

    int s = 0;
    for (int kt = 0; kt <= qt; kt++) {
        cp_wait0();
        __syncthreads();              // stage s ready; prior reads of s^1 done
        if (kt < qt) issue_kv(s ^ 1, kt + 1);

        const unsigned* Ks = fsm + s * KV_STAGE_WORDS;
        const unsigned* Vs = Ks + 64 * FKLD;

        // ---- S = Q K^T ----
        float acc[8][4];
#pragma unroll
        for (int nt = 0; nt < 8; nt++)
#pragma unroll
            for (int i = 0; i < 4; i++) acc[nt][i] = 0.f;

#pragma unroll
        for (int ks = 0; ks < 8; ks++) {
            const int kk = ks * 8 + tig;
#pragma unroll
            for (int nt = 0; nt < 8; nt++) {
                unsigned bb[2];
                bb[0] = Ks[(nt * 8 + gid) * FKLD + kk];
                bb[1] = Ks[(nt * 8 + gid) * FKLD + kk + 4];
                mma_tf32(acc[nt], qf[ks], bb);
            }
        }

        // ---- scale + causal mask (diag tile only) ----
        const bool diag = (kt == qt);
#pragma unroll
        for (int nt = 0; nt < 8; nt++)
#pragma unroll
            for (int i = 0; i < 4; i++) acc[nt][i] *= scale;
        if (diag) {
            const int i0 = m0 + gid;
            const int i1 = m0 + gid + 8;
#pragma unroll
            for (int nt = 0; nt < 8; nt++) {
                int j0 = nt * 8 + 2 * tig, j1 = j0 + 1;
                if (j0 > i0) acc[nt][0] = -INFINITY;
                if (j1 > i0) acc[nt][1] = -INFINITY;
                if (j0 > i1) acc[nt][2] = -INFINITY;
                if (j1 > i1) acc[nt][3] = -INFINITY;
            }
        }

        // ---- online softmax (row spread over 4 tig-lanes) ----
#pragma unroll
        for (int r = 0; r < 2; r++) {
            float mx = -INFINITY;
#pragma unroll
            for (int nt = 0; nt < 8; nt++)
                mx = fmaxf(mx, fmaxf(acc[nt][2 * r], acc[nt][2 * r + 1]));
            mx = fmaxf(mx, __shfl_xor_sync(0xffffffffu, mx, 1));
            mx = fmaxf(mx, __shfl_xor_sync(0xffffffffu, mx, 2));
            float mn = fmaxf(m[r], mx);

            float ls = 0.f;
            const int prow = (m0 + gid + 8 * r) * FKLD;
#pragma unroll
            for (int nt = 0; nt < 8; nt++) {
                float p0 = __expf(acc[nt][2 * r] - mn);
                float p1 = __expf(acc[nt][2 * r + 1] - mn);
                unsigned t0 = f2tf32(p0), t1 = f2tf32(p1);
                ls += __uint_as_float(t0) + __uint_as_float(t1);
                *(uint2*)(Ps + prow + nt * 8 + 2 * tig) = make_uint2(t0, t1);
            }
            ls += __shfl_xor_sync(0xffffffffu, ls, 1);
            ls += __shfl_xor_sync(0xffffffffu, ls, 2);

            float f = __expf(m[r] - mn);
            l[r] = l[r] * f + ls;
            m[r] = mn;
#pragma unroll
            for (int nt = 0; nt < 8; nt++) {
                o[nt][2 * r] *= f;
                o[nt][2 * r + 1] *= f;
            }
        }
        __syncwarp();   // warp-private Ps visible

        // ---- O += P @ V ----
#pragma unroll
        for (int ks = 0; ks < 8; ks++) {
            const int kk = ks * 8 + tig;
            unsigned a[4];
            a[0] = Ps[(m0 + gid) * FKLD + kk];
            a[1] = Ps[(m0 + gid + 8) * FKLD + kk];
            a[2] = Ps[(m0 + gid) * FKLD + kk + 4];
            a[3] = Ps[(m0 + gid + 8) * FKLD + kk + 4];
#pragma unroll
            for (int nt = 0; nt < 8; nt++) {
                unsigned bb[2];
                bb[0] = Vs[kk * FVLD + nt * 8 + gid];
                bb[1] = Vs[(kk + 4) * FVLD + nt * 8 + gid];
                mma_tf32(o[nt], a, bb);
            }
        }
        __syncwarp();   // Ps reads done before next iter's overwrite
        s ^= 1;
    }

    // ---- normalize + write tf32-rounded bits to [tok, h*64+d] ----
    const float inv0 = 1.0f / l[0], inv1 = 1.0f / l[1];
    const int row0 = tokbase + qt * 64 + m0 + gid;
#pragma unroll
    for (int nt = 0; nt < 8; nt++) {
        int col = h * DH + nt * 8 + 2 * tig;
        uint2 v0 = make_uint2(f2tf32(o[nt][0] * inv0), f2tf32(o[nt][1] * inv0));
        uint2 v1 = make_uint2(f2tf32(o[nt][2] * inv1), f2tf32(o[nt][3] * inv1));
        *(uint2*)(attn + (size_t)row0 * D_MODEL + col) = v0;
        *(uint2*)(attn + (size_t)(row0 + 8) * D_MODEL + col) = v1;
    }
}

// ---------------------------------------------------------------------------
// Launch
// ---------------------------------------------------------------------------
extern "C" void kernel_launch(void* const* d_in, const int* in_sizes, int n_in,
                              void* d_out, int out_size) {
    const float* x    = (const float*)d_in[0];   // [2,2048,1024]
    const float* Wqkv = (const float*)d_in[1];   // [1024,3072]
    const float* bqkv = (const float*)d_in[2];   // [3072]
    const float* Wout = (const float*)d_in[3];   // [1024,1024]
    const float* bout = (const float*)d_in[4];   // [1024]
    float* out = (float*)d_out;                  // [2,2048,1024]

    unsigned* qkv;   cudaGetSymbolAddress((void**)&qkv,   g_qkv);
    unsigned* attn;  cudaGetSymbolAddress((void**)&attn,  g_attn);
    unsigned* xt;    cudaGetSymbolAddress((void**)&xt,    g_xt);
    unsigned* wqkvt; cudaGetSymbolAddress((void**)&wqkvt, g_wqkvt);
    unsigned* woutt; cudaGetSymbolAddress((void**)&woutt, g_woutt);

    cudaFuncSetAttribute(tf32_gemm_bias<1>, cudaFuncAttributeMaxDynamicSharedMemorySize,
                         GEMM_SMEM_BYTES);
    cudaFuncSetAttribute(tf32_gemm_bias<0>, cudaFuncAttributeMaxDynamicSharedMemorySize,
                         GEMM_SMEM_BYTES);
    const int flash_smem = FLASH_SMEM_WORDS * (int)sizeof(unsigned);  // 89088 B
    cudaFuncSetAttribute(flash_mma_kernel, cudaFuncAttributeMaxDynamicSharedMemorySize,
                         flash_smem);

    // 0) Pre-convert x, Wqkv, Wout to tf32 bits (single fused launch)
    {
        int n0 = NTOK * D_MODEL / 4;
        int n1 = D_MODEL * QKV_LD / 4;
        int n2 = D_MODEL * D_MODEL / 4;
        int nt = n0 + n1 + n2;
        cvt_tf32_fused<<<(nt + 255) / 256, 256>>>(
            (const float4*)x,    (uint4*)xt,    n0,
            (const float4*)Wqkv, (uint4*)wqkvt, n1,
            (const float4*)Wout, (uint4*)woutt, n2);
    }

    // 1) QKV projection -> tf32 bits (epilogue-rounded for flash)
    {
        dim3 grid(QKV_LD / 128, NTOK / 128);
        tf32_gemm_bias<1><<<grid, 256, GEMM_SMEM_BYTES>>>(xt, wqkvt, bqkv, qkv,
                                                          NTOK, QKV_LD, D_MODEL);
    }

    // 2) Causal flash attention (tf32 tensor cores, Q-in-regs, async K/V)
    {
        dim3 grid(S_LEN / 64, NHEADS, 2);
        flash_mma_kernel<<<grid, 128, flash_smem>>>(qkv, attn);
    }

    // 3) Output projection -> fp32 out
    {
        dim3 grid(D_MODEL / 128, NTOK / 128);
        tf32_gemm_bias<0><<<grid, 256, GEMM_SMEM_BYTES>>>(attn, woutt, bout, out,
                                                          NTOK, D_MODEL, D_MODEL);
    }
}

// round 12
// speedup vs baseline: 1.2673x; 1.0202x over previous
#include <cuda_runtime.h>
#include <cmath>

// Problem constants
#define S_LEN    2048
#define D_MODEL  1024
#define NHEADS   16
#define DH       64
#define QKV_LD   3072   // 3*D
#define NTOK     4096   // B*S

// Scratch (module-static device globals)
__device__ unsigned g_qkv[(size_t)NTOK * QKV_LD];      // tf32-bit qkv projection
__device__ unsigned g_attn[(size_t)NTOK * D_MODEL];    // tf32-bit attention output
__device__ unsigned g_xt[(size_t)NTOK * D_MODEL];      // tf32-bit x
__device__ unsigned g_wqkvt[(size_t)D_MODEL * QKV_LD]; // tf32-bit Wqkv TRANSPOSED [3072][1024]
__device__ unsigned g_woutt[(size_t)D_MODEL * D_MODEL];// tf32-bit Wout TRANSPOSED [1024][1024]

// ---------------------------------------------------------------------------
// helpers
// ---------------------------------------------------------------------------
__device__ __forceinline__ unsigned f2tf32(float x) {
    unsigned u;
    asm("cvt.rna.tf32.f32 %0, %1;" : "=r"(u) : "f"(x));
    return u;
}

// D += A@B, m16n8k8, A row-major, B col-major, fp32 accum
__device__ __forceinline__ void mma_tf32(float* c, const unsigned* a, const unsigned* b) {
    asm volatile(
        "mma.sync.aligned.m16n8k8.row.col.f32.tf32.tf32.f32 "
        "{%0,%1,%2,%3}, {%4,%5,%6,%7}, {%8,%9}, {%0,%1,%2,%3};"
        : "+f"(c[0]), "+f"(c[1]), "+f"(c[2]), "+f"(c[3])
        : "r"(a[0]), "r"(a[1]), "r"(a[2]), "r"(a[3]), "r"(b[0]), "r"(b[1]));
}

__device__ __forceinline__ void ldsm_x4(unsigned& r0, unsigned& r1, unsigned& r2,
                                        unsigned& r3, unsigned addr) {
    asm volatile("ldmatrix.sync.aligned.m8n8.x4.shared.b16 {%0,%1,%2,%3}, [%4];"
                 : "=r"(r0), "=r"(r1), "=r"(r2), "=r"(r3) : "r"(addr));
}

__device__ __forceinline__ void cp_async16(unsigned smem_addr, const void* gptr) {
    asm volatile("cp.async.cg.shared.global [%0], [%1], 16;"
                 :: "r"(smem_addr), "l"(gptr));
}
__device__ __forceinline__ void cp_commit() { asm volatile("cp.async.commit_group;"); }
__device__ __forceinline__ void cp_wait0()  { asm volatile("cp.async.wait_group 0;"); }

// ---------------------------------------------------------------------------
// Pre-pass kernels: tf32 convert (x) and tf32 convert + transpose (weights)
// ---------------------------------------------------------------------------
__global__ void cvt_tf32_kernel(const float4* __restrict__ src,
                                uint4* __restrict__ dst, int n4) {
    int i = blockIdx.x * blockDim.x + threadIdx.x;
    if (i < n4) {
        float4 v = src[i];
        dst[i] = make_uint4(f2tf32(v.x), f2tf32(v.y), f2tf32(v.z), f2tf32(v.w));
    }
}

// src [K][N] fp32 -> dst [N][K] tf32 bits; K,N multiples of 32; 256 threads
__global__ void cvt_t_tf32_kernel(const float* __restrict__ src,
                                  unsigned* __restrict__ dst, int K, int N) {
    __shared__ unsigned sm[32][33];
    const int tx = threadIdx.x & 31, ty = threadIdx.x >> 5;   // 32 x 8
    const int k0 = blockIdx.y * 32, n0 = blockIdx.x * 32;
#pragma unroll
    for (int i = 0; i < 4; i++) {
        int rr = ty + 8 * i;
        sm[tx][rr] = f2tf32(src[(size_t)(k0 + rr) * N + n0 + tx]);
    }
    __syncthreads();
#pragma unroll
    for (int i = 0; i < 4; i++) {
        int rr = ty + 8 * i;
        dst[(size_t)(n0 + rr) * K + k0 + tx] = sm[rr][tx];
    }
}

// ---------------------------------------------------------------------------
// tf32 tensor-core GEMM + bias; A [M][K] tf32 bits, B TRANSPOSED [N][K] tf32 bits.
// cp.async double-buffered; fragments via ldmatrix.x4.
// 128x128 CTA tile, BK=32, 256 threads = 8 warps (4x2), warp tile 32x64.
// As/Bs row stride 36 words -> each 16B ldmatrix row conflict-free.
// ---------------------------------------------------------------------------
#define TS_W 36
#define BUF_WORDS (2 * 128 * TS_W)           // 9216 words per stage
#define GEMM_SMEM_BYTES (2 * BUF_WORDS * 4)  // 73728

template<int TF32OUT>
__global__ __launch_bounds__(256, 2)
void tf32_gemm_bias(const unsigned* __restrict__ A, const unsigned* __restrict__ Bt,
                    const float* __restrict__ bias, void* __restrict__ Cv,
                    int M, int N, int K) {
    extern __shared__ unsigned gsm[];

    const int tid  = threadIdx.x;
    const int warp = tid >> 5, lane = tid & 31;
    const int gid  = lane >> 2, tig = lane & 3;
    const int q8   = lane >> 3, r8 = lane & 7;      // ldmatrix addressing
    const int wrow = warp >> 1, wcol = warp & 1;
    const int bm = blockIdx.y, bn = blockIdx.x;

    // cp.async coords: both A and Bt tiles are 128 rows x 32 cols
    int lrow[4], lcol[4];
#pragma unroll
    for (int c = 0; c < 4; c++) {
        int idx4 = tid + c * 256;
        lrow[c] = idx4 >> 3;  lcol[c] = (idx4 & 7) * 4;
    }

    const unsigned smem_base = (unsigned)__cvta_generic_to_shared(gsm);

    auto issue_tile = [&](int s, int k0) {
        unsigned as_b = smem_base + (unsigned)(s * BUF_WORDS) * 4u;
        unsigned bs_b = as_b + 128u * TS_W * 4u;
#pragma unroll
        for (int c = 0; c < 4; c++) {
            cp_async16(as_b + (unsigned)(lrow[c] * TS_W + lcol[c]) * 4u,
                       A + (size_t)(bm * 128 + lrow[c]) * K + k0 + lcol[c]);
            cp_async16(bs_b + (unsigned)(lrow[c] * TS_W + lcol[c]) * 4u,
                       Bt + (size_t)(bn * 128 + lrow[c]) * K + k0 + lcol[c]);
        }
        cp_commit();
    };

    // ldmatrix per-lane offsets (bytes, within a stage)
    unsigned aOff[2], bOff[4];
#pragma unroll
    for (int mt = 0; mt < 2; mt++)
        aOff[mt] = (unsigned)(((wrow * 32 + mt * 16 + r8 + (q8 & 1) * 8) * TS_W
                              + (q8 >> 1) * 4) * 4);
#pragma unroll
    for (int p = 0; p < 4; p++)
        bOff[p] = (unsigned)((128 * TS_W
                              + (wcol * 64 + p * 16 + r8 + (q8 >> 1) * 8) * TS_W
                              + (q8 & 1) * 4) * 4);

    float acc[2][8][4];
#pragma unroll
    for (int mt = 0; mt < 2; mt++)
#pragma unroll
        for (int nt = 0; nt < 8; nt++)
#pragma unroll
            for (int i = 0; i < 4; i++) acc[mt][nt][i] = 0.f;

    issue_tile(0, 0);

    int s = 0;
    for (int k0 = 0; k0 < K; k0 += 32) {
        cp_wait0();
        __syncthreads();
        if (k0 + 32 < K) issue_tile(s ^ 1, k0 + 32);

        const unsigned stage = smem_base + (unsigned)(s * BUF_WORDS) * 4u;

#pragma unroll
        for (int ks = 0; ks < 4; ks++) {
            unsigned af[2][4];
            ldsm_x4(af[0][0], af[0][1], af[0][2], af[0][3], stage + aOff[0] + ks * 32);
            ldsm_x4(af[1][0], af[1][1], af[1][2], af[1][3], stage + aOff[1] + ks * 32);
            unsigned bf[8][2];
#pragma unroll
            for (int p = 0; p < 4; p++)
                ldsm_x4(bf[2*p][0], bf[2*p][1], bf[2*p+1][0], bf[2*p+1][1],
                        stage + bOff[p] + ks * 32);
#pragma unroll
            for (int mt = 0; mt < 2; mt++)
#pragma unroll
                for (int nt = 0; nt < 8; nt++)
                    mma_tf32(acc[mt][nt], af[mt], bf[nt]);
        }
        s ^= 1;
    }

#pragma unroll
    for (int mt = 0; mt < 2; mt++) {
        int row0 = bm * 128 + wrow * 32 + mt * 16 + gid;
#pragma unroll
        for (int nt = 0; nt < 8; nt++) {
            int col = bn * 128 + wcol * 64 + nt * 8 + tig * 2;
            float2 bv = *(const float2*)(bias + col);
            float c0 = acc[mt][nt][0] + bv.x, c1 = acc[mt][nt][1] + bv.y;
            float c2 = acc[mt][nt][2] + bv.x, c3 = acc[mt][nt][3] + bv.y;
            if (TF32OUT) {
                unsigned* C = (unsigned*)Cv;
                *(uint2*)(C + (size_t)row0 * N + col) = make_uint2(f2tf32(c0), f2tf32(c1));
                *(uint2*)(C + (size_t)(row0 + 8) * N + col) = make_uint2(f2tf32(c2), f2tf32(c3));
            } else {
                float* C = (float*)Cv;
                *(float2*)(C + (size_t)row0 * N + col) = make_float2(c0, c1);
                *(float2*)(C + (size_t)(row0 + 8) * N + col) = make_float2(c2, c3);
            }
        }
    }
}

// ---------------------------------------------------------------------------
// Flash attention, tf32 tensor cores (causal, online softmax).
// R9 structure + ldmatrix fragment loads for Ks (QK B-frags) and Ps (PV A-frags).
// ---------------------------------------------------------------------------
#define FKLD 68
#define FVLD 72
#define KV_STAGE_WORDS (64 * FKLD + 64 * FVLD)            // 8960
#define OFF_PS (2 * KV_STAGE_WORDS)
#define FLASH_SMEM_WORDS (2 * KV_STAGE_WORDS + 64 * FKLD) // 22272 (89088 B)

__global__ __launch_bounds__(128, 2)
void flash_mma_kernel(const unsigned* __restrict__ qkv, unsigned* __restrict__ attn) {
    extern __shared__ unsigned fsm[];
    unsigned* Ps = fsm + OFF_PS;

    const int qt = gridDim.x - 1 - blockIdx.x;   // heavy tiles first
    const int h = blockIdx.y, b = blockIdx.z;
    const int tid = threadIdx.x;
    const int warp = tid >> 5, lane = tid & 31;
    const int gid = lane >> 2, tig = lane & 3;
    const int q8 = lane >> 3, r8 = lane & 7;
    const int m0 = warp * 16;
    const int tokbase = b * S_LEN;
    const float scale = 0.125f;      // 1/sqrt(64)

    // cp.async coords
    int krow[8], kc4[8];
#pragma unroll
    for (int c = 0; c < 8; c++) {
        int i = tid + c * 128;
        krow[c] = i >> 4;  kc4[c] = (i & 15) << 2;
    }

    const unsigned smem_base = (unsigned)__cvta_generic_to_shared(fsm);

    auto issue_kv = [&](int s, int kt) {
        unsigned ks_b = smem_base + (unsigned)(s * KV_STAGE_WORDS) * 4u;
        unsigned vs_b = ks_b + 64u * FKLD * 4u;
#pragma unroll
        for (int c = 0; c < 8; c++) {
            const unsigned* src =
                qkv + (size_t)(tokbase + kt * 64 + krow[c]) * QKV_LD + h * 192;
            cp_async16(ks_b + (unsigned)(krow[c] * FKLD + kc4[c]) * 4u, src + 64 + kc4[c]);
            cp_async16(vs_b + (unsigned)(krow[c] * FVLD + kc4[c]) * 4u, src + 128 + kc4[c]);
        }
        cp_commit();
    };

    // ldmatrix per-lane offsets
    unsigned kOff[4];     // QK B-frags from Ks (seq-major), within stage
#pragma unroll
    for (int p = 0; p < 4; p++)
        kOff[p] = (unsigned)(((p * 16 + r8 + (q8 >> 1) * 8) * FKLD + (q8 & 1) * 4) * 4);
    const unsigned pAddr = smem_base + (unsigned)OFF_PS * 4u
        + (unsigned)(((m0 + r8 + (q8 & 1) * 8) * FKLD + (q8 >> 1) * 4) * 4);

    // ---- Q fragments in registers (loop-invariant) ----
    unsigned qf[8][4];
    {
        const size_t r0 = (size_t)(tokbase + qt * 64 + m0 + gid) * QKV_LD + h * 192;
        const size_t r1 = r0 + 8 * QKV_LD;
#pragma unroll
        for (int ks = 0; ks < 8; ks++) {
            int col = ks * 8 + tig;
            qf[ks][0] = qkv[r0 + col];
            qf[ks][1] = qkv[r1 + col];
            qf[ks][2] = qkv[r0 + col + 4];
            qf[ks][3] = qkv[r1 + col + 4];
        }
    }

    issue_kv(0, 0);

    float o[8][4];
    float m[2], l[2];
#pragma unroll
    for (int nt = 0; nt < 8; nt++)
#pragma unroll
        for (int i = 0; i < 4; i++) o[nt][i] = 0.f;
    m[0] = m[1] = -INFINITY;
    l[0] = l[1] = 0.f;

    int s = 0;
    for (int kt = 0; kt <= qt; kt++) {
        cp_wait0();
        __syncthreads();              // stage s ready; prior reads of s^1 done
        if (kt < qt) issue_kv(s ^ 1, kt + 1);

        const unsigned stage = smem_base + (unsigned)(s * KV_STAGE_WORDS) * 4u;
        const unsigned* Vs = fsm + s * KV_STAGE_WORDS + 64 * FKLD;

        // ---- S = Q K^T (B-frags via ldmatrix) ----
        float acc[8][4];
#pragma unroll
        for (int nt = 0; nt < 8; nt++)
#pragma unroll
            for (int i = 0; i < 4; i++) acc[nt][i] = 0.f;

#pragma unroll
        for (int ks = 0; ks < 8; ks++) {
            unsigned bf[8][2];
#pragma unroll
            for (int p = 0; p < 4; p++)
                ldsm_x4(bf[2*p][0], bf[2*p][1], bf[2*p+1][0], bf[2*p+1][1],
                        stage + kOff[p] + ks * 32);
#pragma unroll
            for (int nt = 0; nt < 8; nt++)
                mma_tf32(acc[nt], qf[ks], bf[nt]);
        }

        // ---- scale + causal mask (diag tile only) ----
        const bool diag = (kt == qt);
#pragma unroll
        for (int nt = 0; nt < 8; nt++)
#pragma unroll
            for (int i = 0; i < 4; i++) acc[nt][i] *= scale;
        if (diag) {
            const int i0 = m0 + gid;
            const int i1 = m0 + gid + 8;
#pragma unroll
            for (int nt = 0; nt < 8; nt++) {
                int j0 = nt * 8 + 2 * tig, j1 = j0 + 1;
                if (j0 > i0) acc[nt][0] = -INFINITY;
                if (j1 > i0) acc[nt][1] = -INFINITY;
                if (j0 > i1) acc[nt][2] = -INFINITY;
                if (j1 > i1) acc[nt][3] = -INFINITY;
            }
        }

        // ---- online softmax (row spread over 4 tig-lanes) ----
#pragma unroll
        for (int r = 0; r < 2; r++) {
            float mx = -INFINITY;
#pragma unroll
            for (int nt = 0; nt < 8; nt++)
                mx = fmaxf(mx, fmaxf(acc[nt][2 * r], acc[nt][2 * r + 1]));
            mx = fmaxf(mx, __shfl_xor_sync(0xffffffffu, mx, 1));
            mx = fmaxf(mx, __shfl_xor_sync(0xffffffffu, mx, 2));
            float mn = fmaxf(m[r], mx);

            float ls = 0.f;
            const int prow = (m0 + gid + 8 * r) * FKLD;
#pragma unroll
            for (int nt = 0; nt < 8; nt++) {
                float p0 = __expf(acc[nt][2 * r] - mn);
                float p1 = __expf(acc[nt][2 * r + 1] - mn);
                unsigned t0 = f2tf32(p0), t1 = f2tf32(p1);
                ls += __uint_as_float(t0) + __uint_as_float(t1);
                *(uint2*)(Ps + prow + nt * 8 + 2 * tig) = make_uint2(t0, t1);
            }
            ls += __shfl_xor_sync(0xffffffffu, ls, 1);
            ls += __shfl_xor_sync(0xffffffffu, ls, 2);

            float f = __expf(m[r] - mn);
            l[r] = l[r] * f + ls;
            m[r] = mn;
#pragma unroll
            for (int nt = 0; nt < 8; nt++) {
                o[nt][2 * r] *= f;
                o[nt][2 * r + 1] *= f;
            }
        }
        __syncwarp();   // warp-private Ps visible

        // ---- O += P @ V (A-frags via ldmatrix) ----
#pragma unroll
        for (int ks = 0; ks < 8; ks++) {
            const int kk = ks * 8 + tig;
            unsigned a[4];
            ldsm_x4(a[0], a[1], a[2], a[3], pAddr + ks * 32);
#pragma unroll
            for (int nt = 0; nt < 8; nt++) {
                unsigned bb[2];
                bb[0] = Vs[kk * FVLD + nt * 8 + gid];
                bb[1] = Vs[(kk + 4) * FVLD + nt * 8 + gid];
                mma_tf32(o[nt], a, bb);
            }
        }
        __syncwarp();   // Ps reads done before next iter's overwrite
        s ^= 1;
    }

    // ---- normalize + write tf32-rounded bits to [tok, h*64+d] ----
    const float inv0 = 1.0f / l[0], inv1 = 1.0f / l[1];
    const int row0 = tokbase + qt * 64 + m0 + gid;
#pragma unroll
    for (int nt = 0; nt < 8; nt++) {
        int col = h * DH + nt * 8 + 2 * tig;
        uint2 v0 = make_uint2(f2tf32(o[nt][0] * inv0), f2tf32(o[nt][1] * inv0));
        uint2 v1 = make_uint2(f2tf32(o[nt][2] * inv1), f2tf32(o[nt][3] * inv1));
        *(uint2*)(attn + (size_t)row0 * D_MODEL + col) = v0;
        *(uint2*)(attn + (size_t)(row0 + 8) * D_MODEL + col) = v1;
    }
}

// ---------------------------------------------------------------------------
// Launch
// ---------------------------------------------------------------------------
extern "C" void kernel_launch(void* const* d_in, const int* in_sizes, int n_in,
                              void* d_out, int out_size) {
    const float* x    = (const float*)d_in[0];   // [2,2048,1024]
    const float* Wqkv = (const float*)d_in[1];   // [1024,3072]
    const float* bqkv = (const float*)d_in[2];   // [3072]
    const float* Wout = (const float*)d_in[3];   // [1024,1024]
    const float* bout = (const float*)d_in[4];   // [1024]
    float* out = (float*)d_out;                  // [2,2048,1024]

    unsigned* qkv;   cudaGetSymbolAddress((void**)&qkv,   g_qkv);
    unsigned* attn;  cudaGetSymbolAddress((void**)&attn,  g_attn);
    unsigned* xt;    cudaGetSymbolAddress((void**)&xt,    g_xt);
    unsigned* wqkvt; cudaGetSymbolAddress((void**)&wqkvt, g_wqkvt);
    unsigned* woutt; cudaGetSymbolAddress((void**)&woutt, g_woutt);

    cudaFuncSetAttribute(tf32_gemm_bias<1>, cudaFuncAttributeMaxDynamicSharedMemorySize,
                         GEMM_SMEM_BYTES);
    cudaFuncSetAttribute(tf32_gemm_bias<0>, cudaFuncAttributeMaxDynamicSharedMemorySize,
                         GEMM_SMEM_BYTES);
    const int flash_smem = FLASH_SMEM_WORDS * (int)sizeof(unsigned);  // 89088 B
    cudaFuncSetAttribute(flash_mma_kernel, cudaFuncAttributeMaxDynamicSharedMemorySize,
                         flash_smem);

    // 0) Pre-convert: x -> tf32 bits; weights -> tf32 bits TRANSPOSED
    {
        int n4 = NTOK * D_MODEL / 4;
        cvt_tf32_kernel<<<(n4 + 255) / 256, 256>>>((const float4*)x, (uint4*)xt, n4);
        dim3 g1(QKV_LD / 32, D_MODEL / 32);
        cvt_t_tf32_kernel<<<g1, 256>>>(Wqkv, wqkvt, D_MODEL, QKV_LD);
        dim3 g2(D_MODEL / 32, D_MODEL / 32);
        cvt_t_tf32_kernel<<<g2, 256>>>(Wout, woutt, D_MODEL, D_MODEL);
    }

    // 1) QKV projection -> tf32 bits (epilogue-rounded for flash)
    {
        dim3 grid(QKV_LD / 128, NTOK / 128);
        tf32_gemm_bias<1><<<grid, 256, GEMM_SMEM_BYTES>>>(xt, wqkvt, bqkv, qkv,
                                                          NTOK, QKV_LD, D_MODEL);
    }

    // 2) Causal flash attention (tf32 tensor cores, ldmatrix fragments)
    {
        dim3 grid(S_LEN / 64, NHEADS, 2);
        flash_mma_kernel<<<grid, 128, flash_smem>>>(qkv, attn);
    }

    // 3) Output projection -> fp32 out
    {
        dim3 grid(D_MODEL / 128, NTOK / 128);
        tf32_gemm_bias<0><<<grid, 256, GEMM_SMEM_BYTES>>>(attn, woutt, bout, out,
                                                          NTOK, D_MODEL, D_MODEL);
    }
}